// round 6
// baseline (speedup 1.0000x reference)
#include <cuda_runtime.h>
#include <math.h>

// Problem constants
#define DIMC    2560
#define NHEAD   40
#define HDIM    64
#define BATCH   2
#define SEQ     2048
#define MROWS   (BATCH * SEQ)                 // 4096
#define QKV_ONE ((size_t)BATCH * NHEAD * SEQ * HDIM)   // 10,485,760 floats per {q,k,v}
#define ATTN_SCALE 0.125f                     // 64^-0.5

// Scratch (allocation-free rule: __device__ globals)
__device__ __align__(16) float g_qkv[3u * BATCH * NHEAD * SEQ * HDIM]; // [which][b][h][n][d]
__device__ __align__(16) float g_attn[(size_t)BATCH * SEQ * DIMC];     // [b][n][h*64+d]

// Swizzle for transposed Q/K tiles in smem: element (d, c) of a 64x64 tile.
// Rotates 16B chunks within each d-row by d so that the S-GEMM float4 reads
// (fixed d, c = 4*tx..) hit 16 distinct chunk positions -> conflict-free.
#define SWZ(d, c) (((d) << 6) + (((((c) >> 2) + (d)) & 15) << 2) + ((c) & 3))

// ---------------------------------------------------------------------------
// SGEMM: C[M, Nout] = A[M, K] @ W[K, Nout] + bias
// MODE 0: A = Ain (x), output scattered into g_qkv [3][B][H][N][D] layout.
// MODE 1: A = g_attn, output = Oout (d_out) row-major.
// Block tile 128x128, BK=16, 256 threads, 8x8 per thread, double-buffered smem.
// ---------------------------------------------------------------------------
template <int MODE>
__global__ __launch_bounds__(256, 2)
void sgemm_kernel(const float* __restrict__ Ain,
                  const float* __restrict__ W,
                  const float* __restrict__ bias,
                  float* __restrict__ Oout,
                  int Nout, int K)
{
    __shared__ float As[2][16][128];   // transposed: As[k][m]
    __shared__ float Bs[2][16][128];   // Bs[k][n]

    const float* A = (MODE == 0) ? Ain : g_attn;
    float*       O = (MODE == 0) ? g_qkv : Oout;

    const int tid = threadIdx.x;
    const int tx  = tid & 15;
    const int ty  = tid >> 4;
    const int bm  = blockIdx.y << 7;
    const int bn  = blockIdx.x << 7;

    // Loader mapping
    const int aRow = tid >> 2;           // 0..63 (plus +64)
    const int aCol = (tid & 3) << 2;     // 0,4,8,12
    const int bRow = tid >> 5;           // 0..7 (plus +8)
    const int bCol = (tid & 31) << 2;    // 0..124

    const float* Aptr = A + (size_t)(bm + aRow) * K + aCol;
    const float* Wptr = W + (size_t)bRow * Nout + bn + bCol;
    const size_t Wstep  = (size_t)16 * Nout;
    const size_t Ahalf  = (size_t)64 * K;
    const size_t Bhalf  = (size_t)8 * Nout;

    float4 ra0 = *(const float4*)Aptr;
    float4 ra1 = *(const float4*)(Aptr + Ahalf);
    float4 rb0 = *(const float4*)Wptr;
    float4 rb1 = *(const float4*)(Wptr + Bhalf);

    As[0][aCol + 0][aRow] = ra0.x; As[0][aCol + 1][aRow] = ra0.y;
    As[0][aCol + 2][aRow] = ra0.z; As[0][aCol + 3][aRow] = ra0.w;
    As[0][aCol + 0][aRow + 64] = ra1.x; As[0][aCol + 1][aRow + 64] = ra1.y;
    As[0][aCol + 2][aRow + 64] = ra1.z; As[0][aCol + 3][aRow + 64] = ra1.w;
    *(float4*)&Bs[0][bRow][bCol]     = rb0;
    *(float4*)&Bs[0][bRow + 8][bCol] = rb1;
    __syncthreads();

    float acc[8][8];
#pragma unroll
    for (int i = 0; i < 8; i++)
#pragma unroll
        for (int j = 0; j < 8; j++) acc[i][j] = 0.0f;

    const int ntiles = K >> 4;
    for (int t = 0; t < ntiles; t++) {
        const int cur = t & 1;
        const bool has_next = (t + 1 < ntiles);
        if (has_next) {
            Aptr += 16;
            Wptr += Wstep;
            ra0 = *(const float4*)Aptr;
            ra1 = *(const float4*)(Aptr + Ahalf);
            rb0 = *(const float4*)Wptr;
            rb1 = *(const float4*)(Wptr + Bhalf);
        }
#pragma unroll
        for (int k = 0; k < 16; k++) {
            const float4 a0 = *(const float4*)&As[cur][k][ty << 3];
            const float4 a1 = *(const float4*)&As[cur][k][(ty << 3) + 4];
            const float4 b0 = *(const float4*)&Bs[cur][k][tx << 3];
            const float4 b1 = *(const float4*)&Bs[cur][k][(tx << 3) + 4];
            const float av[8] = {a0.x, a0.y, a0.z, a0.w, a1.x, a1.y, a1.z, a1.w};
            const float bw[8] = {b0.x, b0.y, b0.z, b0.w, b1.x, b1.y, b1.z, b1.w};
#pragma unroll
            for (int i = 0; i < 8; i++)
#pragma unroll
                for (int j = 0; j < 8; j++)
                    acc[i][j] = fmaf(av[i], bw[j], acc[i][j]);
        }
        if (has_next) {
            const int nxt = cur ^ 1;
            As[nxt][aCol + 0][aRow] = ra0.x; As[nxt][aCol + 1][aRow] = ra0.y;
            As[nxt][aCol + 2][aRow] = ra0.z; As[nxt][aCol + 3][aRow] = ra0.w;
            As[nxt][aCol + 0][aRow + 64] = ra1.x; As[nxt][aCol + 1][aRow + 64] = ra1.y;
            As[nxt][aCol + 2][aRow + 64] = ra1.z; As[nxt][aCol + 3][aRow + 64] = ra1.w;
            *(float4*)&Bs[nxt][bRow][bCol]     = rb0;
            *(float4*)&Bs[nxt][bRow + 8][bCol] = rb1;
        }
        __syncthreads();
    }

    // Epilogue
    if (MODE == 0) {
        // Scatter into g_qkv: col -> (which, h, d); row m -> (b, n)
#pragma unroll
        for (int i = 0; i < 8; i++) {
            const int m  = bm + (ty << 3) + i;
            const int bb = m >> 11;
            const int nn = m & 2047;
#pragma unroll
            for (int jj = 0; jj < 8; jj += 4) {
                const int col   = bn + (tx << 3) + jj;
                const int which = col / DIMC;
                const int cc    = col - which * DIMC;
                const int hh    = cc >> 6;
                const int dd    = cc & 63;
                const float4 bv = *(const float4*)&bias[col];
                float4 v;
                v.x = acc[i][jj + 0] + bv.x;
                v.y = acc[i][jj + 1] + bv.y;
                v.z = acc[i][jj + 2] + bv.z;
                v.w = acc[i][jj + 3] + bv.w;
                const size_t o = ((((size_t)which * BATCH + bb) * NHEAD + hh) * SEQ + nn) * HDIM + dd;
                *(float4*)(O + o) = v;
            }
        }
    } else {
#pragma unroll
        for (int i = 0; i < 8; i++) {
            const int m = bm + (ty << 3) + i;
#pragma unroll
            for (int jj = 0; jj < 8; jj += 4) {
                const int col   = bn + (tx << 3) + jj;
                const float4 bv = *(const float4*)&bias[col];
                float4 v;
                v.x = acc[i][jj + 0] + bv.x;
                v.y = acc[i][jj + 1] + bv.y;
                v.z = acc[i][jj + 2] + bv.z;
                v.w = acc[i][jj + 3] + bv.w;
                *(float4*)&O[(size_t)m * Nout + col] = v;
            }
        }
    }
}

// ---------------------------------------------------------------------------
// Flash attention, fp32. One block = one (b, h, 64-query tile).
// 256 threads as 16x16; each thread owns a 4(row) x 4(col) fragment.
// Qt/KP hold transposed+swizzled tiles for the S-GEMM (inner dim = d);
// KP is reused as the P tile (row-major) for the PV GEMM (inner dim = key).
// ---------------------------------------------------------------------------
__global__ __launch_bounds__(256)
void attn_kernel()
{
    __shared__ float Qt[64 * 64];   // swizzled transposed, pre-scaled Q
    __shared__ float KP[64 * 64];   // K (swizzled transposed) -> then P[r][c]
    __shared__ float Vs[64 * 64];   // V[key][d], natural layout

    const int tid = threadIdx.x;
    const int tx  = tid & 15;
    const int ty  = tid >> 4;
    const int q0  = blockIdx.x << 6;
    const int h   = blockIdx.y;
    const int b   = blockIdx.z;

    const size_t bh = ((size_t)b * NHEAD + h) * ((size_t)SEQ * HDIM);
    const float* Qg = g_qkv + bh + (size_t)q0 * HDIM;
    const float* Kg = g_qkv + QKV_ONE + bh;
    const float* Vg = g_qkv + 2 * QKV_ONE + bh;

    // Load Q tile: transpose + swizzle + pre-scale
#pragma unroll
    for (int p = 0; p < 4; p++) {
        const int idx = tid + (p << 8);
        const int row = idx >> 4;
        const int c4  = (idx & 15) << 2;
        const float4 v = *(const float4*)(Qg + (row << 6) + c4);
        Qt[SWZ(c4 + 0, row)] = v.x * ATTN_SCALE;
        Qt[SWZ(c4 + 1, row)] = v.y * ATTN_SCALE;
        Qt[SWZ(c4 + 2, row)] = v.z * ATTN_SCALE;
        Qt[SWZ(c4 + 3, row)] = v.w * ATTN_SCALE;
    }

    float Oacc[4][4];
#pragma unroll
    for (int i = 0; i < 4; i++)
#pragma unroll
        for (int j = 0; j < 4; j++) Oacc[i][j] = 0.0f;
    float mrow[4] = {-1e30f, -1e30f, -1e30f, -1e30f};
    float lrow[4] = {0.0f, 0.0f, 0.0f, 0.0f};

    for (int kt = 0; kt < SEQ / 64; kt++) {
        __syncthreads();   // prev iter done with KP/Vs (and Qt visible on iter 0)

        const float* Kt = Kg + ((size_t)(kt << 6)) * HDIM;
        const float* Vt = Vg + ((size_t)(kt << 6)) * HDIM;
#pragma unroll
        for (int p = 0; p < 4; p++) {
            const int idx = tid + (p << 8);
            const int row = idx >> 4;
            const int c4  = (idx & 15) << 2;
            const float4 kv = *(const float4*)(Kt + (row << 6) + c4);
            KP[SWZ(c4 + 0, row)] = kv.x;
            KP[SWZ(c4 + 1, row)] = kv.y;
            KP[SWZ(c4 + 2, row)] = kv.z;
            KP[SWZ(c4 + 3, row)] = kv.w;
            *(float4*)&Vs[(row << 6) + c4] = *(const float4*)(Vt + (row << 6) + c4);
        }
        __syncthreads();   // tiles ready

        // S = Q K^T (pre-scaled), 4x4 fragment per thread
        float s[4][4];
#pragma unroll
        for (int i = 0; i < 4; i++)
#pragma unroll
            for (int j = 0; j < 4; j++) s[i][j] = 0.0f;

#pragma unroll 16
        for (int d = 0; d < 64; d++) {
            const float4 aq = *(const float4*)&Qt[(d << 6) + (((ty + d) & 15) << 2)];
            const float4 bk = *(const float4*)&KP[(d << 6) + (((tx + d) & 15) << 2)];
            const float av[4] = {aq.x, aq.y, aq.z, aq.w};
            const float bv[4] = {bk.x, bk.y, bk.z, bk.w};
#pragma unroll
            for (int i = 0; i < 4; i++)
#pragma unroll
                for (int j = 0; j < 4; j++)
                    s[i][j] = fmaf(av[i], bv[j], s[i][j]);
        }

        // Online softmax: rows are shared by the 16 threads with the same ty.
#pragma unroll
        for (int i = 0; i < 4; i++) {
            float rmax = fmaxf(fmaxf(s[i][0], s[i][1]), fmaxf(s[i][2], s[i][3]));
#pragma unroll
            for (int off = 8; off > 0; off >>= 1)
                rmax = fmaxf(rmax, __shfl_xor_sync(0xffffffffu, rmax, off));
            const float mnew  = fmaxf(mrow[i], rmax);
            const float alpha = __expf(mrow[i] - mnew);
            mrow[i] = mnew;
            float rsum = 0.0f;
#pragma unroll
            for (int j = 0; j < 4; j++) {
                s[i][j] = __expf(s[i][j] - mnew);
                rsum += s[i][j];
            }
#pragma unroll
            for (int off = 8; off > 0; off >>= 1)
                rsum += __shfl_xor_sync(0xffffffffu, rsum, off);
            lrow[i] = lrow[i] * alpha + rsum;
#pragma unroll
            for (int j = 0; j < 4; j++) Oacc[i][j] *= alpha;
        }

        __syncthreads();   // everyone done reading KP as K
#pragma unroll
        for (int i = 0; i < 4; i++) {
            const float4 pv = make_float4(s[i][0], s[i][1], s[i][2], s[i][3]);
            *(float4*)&KP[(((ty << 2) + i) << 6) + (tx << 2)] = pv;
        }
        __syncthreads();   // P visible

        // O += P @ V   (inner dim = key index c)
#pragma unroll
        for (int c0 = 0; c0 < 64; c0 += 4) {
            float4 pa[4];
#pragma unroll
            for (int i = 0; i < 4; i++)
                pa[i] = *(const float4*)&KP[(((ty << 2) + i) << 6) + c0];
#pragma unroll
            for (int cc = 0; cc < 4; cc++) {
                const float4 vb = *(const float4*)&Vs[((c0 + cc) << 6) + (tx << 2)];
                const float bv[4] = {vb.x, vb.y, vb.z, vb.w};
#pragma unroll
                for (int i = 0; i < 4; i++) {
                    const float pval = (cc == 0) ? pa[i].x :
                                       (cc == 1) ? pa[i].y :
                                       (cc == 2) ? pa[i].z : pa[i].w;
#pragma unroll
                    for (int j = 0; j < 4; j++)
                        Oacc[i][j] = fmaf(pval, bv[j], Oacc[i][j]);
                }
            }
        }
    }

    // Epilogue: O / l -> g_attn[b][n][h*64 + d]
#pragma unroll
    for (int i = 0; i < 4; i++) {
        const float inv = 1.0f / lrow[i];
        const int n = q0 + (ty << 2) + i;
        float4 ov;
        ov.x = Oacc[i][0] * inv;
        ov.y = Oacc[i][1] * inv;
        ov.z = Oacc[i][2] * inv;
        ov.w = Oacc[i][3] * inv;
        *(float4*)&g_attn[((size_t)b * SEQ + n) * DIMC + h * HDIM + (tx << 2)] = ov;
    }
}

// ---------------------------------------------------------------------------
extern "C" void kernel_launch(void* const* d_in, const int* in_sizes, int n_in,
                              void* d_out, int out_size)
{
    (void)in_sizes; (void)n_in; (void)out_size;
    const float* x      = (const float*)d_in[0];
    const float* w_qkv  = (const float*)d_in[1];
    const float* b_qkv  = (const float*)d_in[2];
    const float* w_proj = (const float*)d_in[3];
    const float* b_proj = (const float*)d_in[4];
    float* out = (float*)d_out;

    // 1) QKV GEMM: [4096, 2560] @ [2560, 7680] + bias -> g_qkv [3][B][H][N][D]
    {
        dim3 grid(3 * DIMC / 128, MROWS / 128);   // (60, 32)
        sgemm_kernel<0><<<grid, 256>>>(x, w_qkv, b_qkv, nullptr, 3 * DIMC, DIMC);
    }

    // 2) Attention per (b, h, q-tile) -> g_attn [B][N][C]
    {
        dim3 grid(SEQ / 64, NHEAD, BATCH);        // (32, 40, 2)
        attn_kernel<<<grid, 256>>>();
    }

    // 3) Output projection: [4096, 2560] @ [2560, 2560] + bias -> d_out
    {
        dim3 grid(DIMC / 128, MROWS / 128);       // (20, 32)
        sgemm_kernel<1><<<grid, 256>>>(nullptr, w_proj, b_proj, out, DIMC, DIMC);
    }
}

// round 8
// speedup vs baseline: 1.5254x; 1.5254x over previous
#include <cuda_runtime.h>
#include <cstdint>
#include <math.h>

// Problem constants
#define DIMC    2560
#define NHEAD   40
#define HDIM    64
#define BATCH   2
#define SEQ     2048
#define MROWS   (BATCH * SEQ)                 // 4096
#define QKV_ONE ((size_t)BATCH * NHEAD * SEQ * HDIM)
#define ATTN_SCALE 0.125f

// Scratch (allocation-free rule: __device__ globals)
__device__ __align__(16) float g_qkv[3u * BATCH * NHEAD * SEQ * HDIM]; // [which][b][h][n][d]
__device__ __align__(16) float g_attn[(size_t)BATCH * SEQ * DIMC];     // [b][n][h*64+d]

// ---------------------------------------------------------------------------
// mma.sync tf32 helpers (sm_80+ PTX, compiles for plain compute_103)
// ---------------------------------------------------------------------------
__device__ __forceinline__ float f2tf32(float x) {
    uint32_t u;
    asm("cvt.rna.tf32.f32 %0, %1;" : "=r"(u) : "f"(x));
    return __uint_as_float(u);
}
__device__ __forceinline__ void mma_tf32(float* c, const uint32_t* a,
                                         uint32_t b0, uint32_t b1) {
    asm volatile(
        "mma.sync.aligned.m16n8k8.row.col.f32.tf32.tf32.f32 "
        "{%0,%1,%2,%3}, {%4,%5,%6,%7}, {%8,%9}, {%0,%1,%2,%3};"
        : "+f"(c[0]), "+f"(c[1]), "+f"(c[2]), "+f"(c[3])
        : "r"(a[0]), "r"(a[1]), "r"(a[2]), "r"(a[3]), "r"(b0), "r"(b1));
}

// ---------------------------------------------------------------------------
// TF32 tensor-core GEMM: C[M, Nout] = A[M, 2560] @ W[2560, Nout] + bias
// MODE 0: A = Ain (x), scatter into g_qkv [3][B][H][N][D]
// MODE 1: A = g_attn, row-major to Oout
// CTA 128x128, BK=32, 256 threads (8 warps, 4Mx2N), double-buffered smem.
// smem rows padded to 36 floats: fragment LDS bank = (4*(lane>>2) + k) & 31
// covers 32 distinct banks -> conflict-free.
// ---------------------------------------------------------------------------
#define SM_STRIDE   36
#define SM_TILE     (128 * SM_STRIDE)            // floats per A or B tile
#define SM_STAGE    (2 * SM_TILE)                // A + B, one stage
#define GEMM_SMEM_BYTES (2 * SM_STAGE * 4)       // 73728 bytes

template <int MODE>
__global__ __launch_bounds__(256, 2)
void mma_gemm(const float* __restrict__ Ain, const float* __restrict__ W,
              const float* __restrict__ bias, float* __restrict__ Oout, int Nout)
{
    extern __shared__ float sm[];
    const int tid  = threadIdx.x;
    const int wid  = tid >> 5;
    const int lane = tid & 31;
    const int q    = lane >> 2;      // group id 0..7
    const int lp   = lane & 3;       // thread-in-group
    const int warp_m = wid & 3;      // 0..3 -> 32-row strip
    const int warp_n = wid >> 2;     // 0..1 -> 64-col strip
    const int bm = blockIdx.x << 7;
    const int bn = blockIdx.y << 7;
    const int K  = DIMC;
    const int nch = K / 32;          // 80

    const float* A = (MODE == 0) ? Ain : g_attn;

    // Global loader mapping
    const int aM  = tid >> 3;                 // A: rows, +32 per p
    const int aC4 = (tid & 7) << 2;           // A: k offset
    const int bK  = tid & 7;                  // B: k, +8 per p
    const int bN  = (tid >> 3) << 2;          // B: n group of 4

    float4 va[4], vb[4];
#pragma unroll
    for (int p = 0; p < 4; p++) {
        va[p] = *(const float4*)&A[(size_t)(bm + aM + (p << 5)) * K + aC4];
        vb[p] = *(const float4*)&W[(size_t)(bK + (p << 3)) * Nout + bn + bN];
    }

    float acc[2][8][4];
#pragma unroll
    for (int mi = 0; mi < 2; mi++)
#pragma unroll
        for (int nj = 0; nj < 8; nj++)
#pragma unroll
            for (int r = 0; r < 4; r++) acc[mi][nj][r] = 0.0f;

    // stage 0 STS
    {
        float* As = sm;
        float* Bs = sm + SM_TILE;
#pragma unroll
        for (int p = 0; p < 4; p++) {
            float4 t;
            t.x = f2tf32(va[p].x); t.y = f2tf32(va[p].y);
            t.z = f2tf32(va[p].z); t.w = f2tf32(va[p].w);
            *(float4*)&As[(aM + (p << 5)) * SM_STRIDE + aC4] = t;
            const int k = bK + (p << 3);
            Bs[(bN + 0) * SM_STRIDE + k] = f2tf32(vb[p].x);
            Bs[(bN + 1) * SM_STRIDE + k] = f2tf32(vb[p].y);
            Bs[(bN + 2) * SM_STRIDE + k] = f2tf32(vb[p].z);
            Bs[(bN + 3) * SM_STRIDE + k] = f2tf32(vb[p].w);
        }
    }
    __syncthreads();

    for (int c = 0; c < nch; c++) {
        const int cur = c & 1;
        const bool has_next = (c + 1 < nch);
        if (has_next) {
            const int kc = (c + 1) << 5;
#pragma unroll
            for (int p = 0; p < 4; p++) {
                va[p] = *(const float4*)&A[(size_t)(bm + aM + (p << 5)) * K + kc + aC4];
                vb[p] = *(const float4*)&W[(size_t)(kc + bK + (p << 3)) * Nout + bn + bN];
            }
        }

        // Compute on cur stage
        {
            const float* As = sm + cur * SM_STAGE;
            const float* Bs = As + SM_TILE;
#pragma unroll
            for (int ks = 0; ks < 4; ks++) {
                const int kcol = (ks << 3) + lp;
                uint32_t a[2][4];
#pragma unroll
                for (int mi = 0; mi < 2; mi++) {
                    const int r0 = (warp_m << 5) + (mi << 4) + q;
                    a[mi][0] = __float_as_uint(As[r0 * SM_STRIDE + kcol]);
                    a[mi][1] = __float_as_uint(As[(r0 + 8) * SM_STRIDE + kcol]);
                    a[mi][2] = __float_as_uint(As[r0 * SM_STRIDE + kcol + 4]);
                    a[mi][3] = __float_as_uint(As[(r0 + 8) * SM_STRIDE + kcol + 4]);
                }
#pragma unroll
                for (int nj = 0; nj < 8; nj++) {
                    const int n = (warp_n << 6) + (nj << 3) + q;
                    const uint32_t b0 = __float_as_uint(Bs[n * SM_STRIDE + kcol]);
                    const uint32_t b1 = __float_as_uint(Bs[n * SM_STRIDE + kcol + 4]);
                    mma_tf32(acc[0][nj], a[0], b0, b1);
                    mma_tf32(acc[1][nj], a[1], b0, b1);
                }
            }
        }

        if (has_next) {
            float* As = sm + (cur ^ 1) * SM_STAGE;
            float* Bs = As + SM_TILE;
#pragma unroll
            for (int p = 0; p < 4; p++) {
                float4 t;
                t.x = f2tf32(va[p].x); t.y = f2tf32(va[p].y);
                t.z = f2tf32(va[p].z); t.w = f2tf32(va[p].w);
                *(float4*)&As[(aM + (p << 5)) * SM_STRIDE + aC4] = t;
                const int k = bK + (p << 3);
                Bs[(bN + 0) * SM_STRIDE + k] = f2tf32(vb[p].x);
                Bs[(bN + 1) * SM_STRIDE + k] = f2tf32(vb[p].y);
                Bs[(bN + 2) * SM_STRIDE + k] = f2tf32(vb[p].z);
                Bs[(bN + 3) * SM_STRIDE + k] = f2tf32(vb[p].w);
            }
        }
        __syncthreads();
    }

    // Epilogue. c0,c1 -> row r, cols 2lp,2lp+1 ; c2,c3 -> row r+8.
#pragma unroll
    for (int mi = 0; mi < 2; mi++) {
        const int row0 = bm + (warp_m << 5) + (mi << 4) + q;
#pragma unroll
        for (int nj = 0; nj < 8; nj++) {
            const int col = bn + (warp_n << 6) + (nj << 3) + (lp << 1);
            const float bx = bias[col];
            const float by = bias[col + 1];
            float2 v0 = make_float2(acc[mi][nj][0] + bx, acc[mi][nj][1] + by);
            float2 v1 = make_float2(acc[mi][nj][2] + bx, acc[mi][nj][3] + by);
            if (MODE == 0) {
                const int which = col / DIMC;
                const int cc = col - which * DIMC;
                const int hh = cc >> 6;
                const int dd = cc & 63;
                const int bb0 = row0 >> 11, nn0 = row0 & 2047;
                const int r1 = row0 + 8;
                const int bb1 = r1 >> 11, nn1 = r1 & 2047;
                const size_t base = (((size_t)which * BATCH) * NHEAD + hh) * SEQ * HDIM;
                *(float2*)&g_qkv[base + (((size_t)bb0 * NHEAD * SEQ) + nn0) * HDIM + dd] = v0;
                *(float2*)&g_qkv[base + (((size_t)bb1 * NHEAD * SEQ) + nn1) * HDIM + dd] = v1;
            } else {
                *(float2*)&Oout[(size_t)row0 * Nout + col] = v0;
                *(float2*)&Oout[(size_t)(row0 + 8) * Nout + col] = v1;
            }
        }
    }
}

// ---------------------------------------------------------------------------
// Flash attention, fp32 (unchanged from R5 — exact, isolates tf32 error)
// ---------------------------------------------------------------------------
#define SWZ(d, c) (((d) << 6) + (((((c) >> 2) + (d)) & 15) << 2) + ((c) & 3))

__global__ __launch_bounds__(256)
void attn_kernel()
{
    __shared__ float Qt[64 * 64];
    __shared__ float KP[64 * 64];
    __shared__ float Vs[64 * 64];

    const int tid = threadIdx.x;
    const int tx  = tid & 15;
    const int ty  = tid >> 4;
    const int q0  = blockIdx.x << 6;
    const int h   = blockIdx.y;
    const int b   = blockIdx.z;

    const size_t bh = ((size_t)b * NHEAD + h) * ((size_t)SEQ * HDIM);
    const float* Qg = g_qkv + bh + (size_t)q0 * HDIM;
    const float* Kg = g_qkv + QKV_ONE + bh;
    const float* Vg = g_qkv + 2 * QKV_ONE + bh;

#pragma unroll
    for (int p = 0; p < 4; p++) {
        const int idx = tid + (p << 8);
        const int row = idx >> 4;
        const int c4  = (idx & 15) << 2;
        const float4 v = *(const float4*)(Qg + (row << 6) + c4);
        Qt[SWZ(c4 + 0, row)] = v.x * ATTN_SCALE;
        Qt[SWZ(c4 + 1, row)] = v.y * ATTN_SCALE;
        Qt[SWZ(c4 + 2, row)] = v.z * ATTN_SCALE;
        Qt[SWZ(c4 + 3, row)] = v.w * ATTN_SCALE;
    }

    float Oacc[4][4];
#pragma unroll
    for (int i = 0; i < 4; i++)
#pragma unroll
        for (int j = 0; j < 4; j++) Oacc[i][j] = 0.0f;
    float mrow[4] = {-1e30f, -1e30f, -1e30f, -1e30f};
    float lrow[4] = {0.0f, 0.0f, 0.0f, 0.0f};

    for (int kt = 0; kt < SEQ / 64; kt++) {
        __syncthreads();

        const float* Kt = Kg + ((size_t)(kt << 6)) * HDIM;
        const float* Vt = Vg + ((size_t)(kt << 6)) * HDIM;
#pragma unroll
        for (int p = 0; p < 4; p++) {
            const int idx = tid + (p << 8);
            const int row = idx >> 4;
            const int c4  = (idx & 15) << 2;
            const float4 kv = *(const float4*)(Kt + (row << 6) + c4);
            KP[SWZ(c4 + 0, row)] = kv.x;
            KP[SWZ(c4 + 1, row)] = kv.y;
            KP[SWZ(c4 + 2, row)] = kv.z;
            KP[SWZ(c4 + 3, row)] = kv.w;
            *(float4*)&Vs[(row << 6) + c4] = *(const float4*)(Vt + (row << 6) + c4);
        }
        __syncthreads();

        float s[4][4];
#pragma unroll
        for (int i = 0; i < 4; i++)
#pragma unroll
            for (int j = 0; j < 4; j++) s[i][j] = 0.0f;

#pragma unroll 16
        for (int d = 0; d < 64; d++) {
            const float4 aq = *(const float4*)&Qt[(d << 6) + (((ty + d) & 15) << 2)];
            const float4 bk = *(const float4*)&KP[(d << 6) + (((tx + d) & 15) << 2)];
            const float av[4] = {aq.x, aq.y, aq.z, aq.w};
            const float bv[4] = {bk.x, bk.y, bk.z, bk.w};
#pragma unroll
            for (int i = 0; i < 4; i++)
#pragma unroll
                for (int j = 0; j < 4; j++)
                    s[i][j] = fmaf(av[i], bv[j], s[i][j]);
        }

#pragma unroll
        for (int i = 0; i < 4; i++) {
            float rmax = fmaxf(fmaxf(s[i][0], s[i][1]), fmaxf(s[i][2], s[i][3]));
#pragma unroll
            for (int off = 8; off > 0; off >>= 1)
                rmax = fmaxf(rmax, __shfl_xor_sync(0xffffffffu, rmax, off));
            const float mnew  = fmaxf(mrow[i], rmax);
            const float alpha = __expf(mrow[i] - mnew);
            mrow[i] = mnew;
            float rsum = 0.0f;
#pragma unroll
            for (int j = 0; j < 4; j++) {
                s[i][j] = __expf(s[i][j] - mnew);
                rsum += s[i][j];
            }
#pragma unroll
            for (int off = 8; off > 0; off >>= 1)
                rsum += __shfl_xor_sync(0xffffffffu, rsum, off);
            lrow[i] = lrow[i] * alpha + rsum;
#pragma unroll
            for (int j = 0; j < 4; j++) Oacc[i][j] *= alpha;
        }

        __syncthreads();
#pragma unroll
        for (int i = 0; i < 4; i++) {
            const float4 pv = make_float4(s[i][0], s[i][1], s[i][2], s[i][3]);
            *(float4*)&KP[(((ty << 2) + i) << 6) + (tx << 2)] = pv;
        }
        __syncthreads();

#pragma unroll
        for (int c0 = 0; c0 < 64; c0 += 4) {
            float4 pa[4];
#pragma unroll
            for (int i = 0; i < 4; i++)
                pa[i] = *(const float4*)&KP[(((ty << 2) + i) << 6) + c0];
#pragma unroll
            for (int cc = 0; cc < 4; cc++) {
                const float4 vb = *(const float4*)&Vs[((c0 + cc) << 6) + (tx << 2)];
                const float bv[4] = {vb.x, vb.y, vb.z, vb.w};
#pragma unroll
                for (int i = 0; i < 4; i++) {
                    const float pval = (cc == 0) ? pa[i].x :
                                       (cc == 1) ? pa[i].y :
                                       (cc == 2) ? pa[i].z : pa[i].w;
#pragma unroll
                    for (int j = 0; j < 4; j++)
                        Oacc[i][j] = fmaf(pval, bv[j], Oacc[i][j]);
                }
            }
        }
    }

#pragma unroll
    for (int i = 0; i < 4; i++) {
        const float inv = 1.0f / lrow[i];
        const int n = q0 + (ty << 2) + i;
        float4 ov;
        ov.x = Oacc[i][0] * inv;
        ov.y = Oacc[i][1] * inv;
        ov.z = Oacc[i][2] * inv;
        ov.w = Oacc[i][3] * inv;
        *(float4*)&g_attn[((size_t)b * SEQ + n) * DIMC + h * HDIM + (tx << 2)] = ov;
    }
}

// ---------------------------------------------------------------------------
extern "C" void kernel_launch(void* const* d_in, const int* in_sizes, int n_in,
                              void* d_out, int out_size)
{
    (void)in_sizes; (void)n_in; (void)out_size;
    const float* x      = (const float*)d_in[0];
    const float* w_qkv  = (const float*)d_in[1];
    const float* b_qkv  = (const float*)d_in[2];
    const float* w_proj = (const float*)d_in[3];
    const float* b_proj = (const float*)d_in[4];
    float* out = (float*)d_out;

    cudaFuncSetAttribute(mma_gemm<0>, cudaFuncAttributeMaxDynamicSharedMemorySize, GEMM_SMEM_BYTES);
    cudaFuncSetAttribute(mma_gemm<1>, cudaFuncAttributeMaxDynamicSharedMemorySize, GEMM_SMEM_BYTES);

    // 1) QKV GEMM (tf32 mma.sync): [4096,2560]@[2560,7680]+bias -> g_qkv
    {
        dim3 grid(MROWS / 128, 3 * DIMC / 128);   // (32, 60)
        mma_gemm<0><<<grid, 256, GEMM_SMEM_BYTES>>>(x, w_qkv, b_qkv, nullptr, 3 * DIMC);
    }
    // 2) Attention (exact fp32) -> g_attn
    {
        dim3 grid(SEQ / 64, NHEAD, BATCH);
        attn_kernel<<<grid, 256>>>();
    }
    // 3) Projection GEMM (tf32 mma.sync): [4096,2560]@[2560,2560]+bias -> d_out
    {
        dim3 grid(MROWS / 128, DIMC / 128);
        mma_gemm<1><<<grid, 256, GEMM_SMEM_BYTES>>>(nullptr, w_proj, b_proj, out, DIMC);
    }
}

// round 9
// speedup vs baseline: 2.3113x; 1.5152x over previous
#include <cuda_runtime.h>
#include <cstdint>
#include <math.h>

// Problem constants
#define DIMC    2560
#define NHEAD   40
#define HDIM    64
#define BATCH   2
#define SEQ     2048
#define MROWS   (BATCH * SEQ)                 // 4096
#define QKV_ONE ((size_t)BATCH * NHEAD * SEQ * HDIM)
#define ATTN_SCALE 0.125f

// Scratch (allocation-free rule: __device__ globals)
__device__ __align__(16) float g_qkv[3u * BATCH * NHEAD * SEQ * HDIM]; // [which][b][h][n][d]
__device__ __align__(16) float g_attn[(size_t)BATCH * SEQ * DIMC];     // [b][n][h*64+d]

// ---------------------------------------------------------------------------
// mma.sync tf32 helpers (sm_80+ PTX, compiles for plain compute_103)
// ---------------------------------------------------------------------------
__device__ __forceinline__ float f2tf32(float x) {
    uint32_t u;
    asm("cvt.rna.tf32.f32 %0, %1;" : "=r"(u) : "f"(x));
    return __uint_as_float(u);
}
__device__ __forceinline__ void mma_tf32(float* c, const uint32_t* a,
                                         uint32_t b0, uint32_t b1) {
    asm volatile(
        "mma.sync.aligned.m16n8k8.row.col.f32.tf32.tf32.f32 "
        "{%0,%1,%2,%3}, {%4,%5,%6,%7}, {%8,%9}, {%0,%1,%2,%3};"
        : "+f"(c[0]), "+f"(c[1]), "+f"(c[2]), "+f"(c[3])
        : "r"(a[0]), "r"(a[1]), "r"(a[2]), "r"(a[3]), "r"(b0), "r"(b1));
}

// ---------------------------------------------------------------------------
// TF32 tensor-core GEMM (unchanged from R7 — measured 103 TF/s)
// ---------------------------------------------------------------------------
#define SM_STRIDE   36
#define SM_TILE     (128 * SM_STRIDE)
#define SM_STAGE    (2 * SM_TILE)
#define GEMM_SMEM_BYTES (2 * SM_STAGE * 4)

template <int MODE>
__global__ __launch_bounds__(256, 2)
void mma_gemm(const float* __restrict__ Ain, const float* __restrict__ W,
              const float* __restrict__ bias, float* __restrict__ Oout, int Nout)
{
    extern __shared__ float sm[];
    const int tid  = threadIdx.x;
    const int wid  = tid >> 5;
    const int lane = tid & 31;
    const int q    = lane >> 2;
    const int lp   = lane & 3;
    const int warp_m = wid & 3;
    const int warp_n = wid >> 2;
    const int bm = blockIdx.x << 7;
    const int bn = blockIdx.y << 7;
    const int K  = DIMC;
    const int nch = K / 32;

    const float* A = (MODE == 0) ? Ain : g_attn;

    const int aM  = tid >> 3;
    const int aC4 = (tid & 7) << 2;
    const int bK  = tid & 7;
    const int bN  = (tid >> 3) << 2;

    float4 va[4], vb[4];
#pragma unroll
    for (int p = 0; p < 4; p++) {
        va[p] = *(const float4*)&A[(size_t)(bm + aM + (p << 5)) * K + aC4];
        vb[p] = *(const float4*)&W[(size_t)(bK + (p << 3)) * Nout + bn + bN];
    }

    float acc[2][8][4];
#pragma unroll
    for (int mi = 0; mi < 2; mi++)
#pragma unroll
        for (int nj = 0; nj < 8; nj++)
#pragma unroll
            for (int r = 0; r < 4; r++) acc[mi][nj][r] = 0.0f;

    {
        float* As = sm;
        float* Bs = sm + SM_TILE;
#pragma unroll
        for (int p = 0; p < 4; p++) {
            float4 t;
            t.x = f2tf32(va[p].x); t.y = f2tf32(va[p].y);
            t.z = f2tf32(va[p].z); t.w = f2tf32(va[p].w);
            *(float4*)&As[(aM + (p << 5)) * SM_STRIDE + aC4] = t;
            const int k = bK + (p << 3);
            Bs[(bN + 0) * SM_STRIDE + k] = f2tf32(vb[p].x);
            Bs[(bN + 1) * SM_STRIDE + k] = f2tf32(vb[p].y);
            Bs[(bN + 2) * SM_STRIDE + k] = f2tf32(vb[p].z);
            Bs[(bN + 3) * SM_STRIDE + k] = f2tf32(vb[p].w);
        }
    }
    __syncthreads();

    for (int c = 0; c < nch; c++) {
        const int cur = c & 1;
        const bool has_next = (c + 1 < nch);
        if (has_next) {
            const int kc = (c + 1) << 5;
#pragma unroll
            for (int p = 0; p < 4; p++) {
                va[p] = *(const float4*)&A[(size_t)(bm + aM + (p << 5)) * K + kc + aC4];
                vb[p] = *(const float4*)&W[(size_t)(kc + bK + (p << 3)) * Nout + bn + bN];
            }
        }
        {
            const float* As = sm + cur * SM_STAGE;
            const float* Bs = As + SM_TILE;
#pragma unroll
            for (int ks = 0; ks < 4; ks++) {
                const int kcol = (ks << 3) + lp;
                uint32_t a[2][4];
#pragma unroll
                for (int mi = 0; mi < 2; mi++) {
                    const int r0 = (warp_m << 5) + (mi << 4) + q;
                    a[mi][0] = __float_as_uint(As[r0 * SM_STRIDE + kcol]);
                    a[mi][1] = __float_as_uint(As[(r0 + 8) * SM_STRIDE + kcol]);
                    a[mi][2] = __float_as_uint(As[r0 * SM_STRIDE + kcol + 4]);
                    a[mi][3] = __float_as_uint(As[(r0 + 8) * SM_STRIDE + kcol + 4]);
                }
#pragma unroll
                for (int nj = 0; nj < 8; nj++) {
                    const int n = (warp_n << 6) + (nj << 3) + q;
                    const uint32_t b0 = __float_as_uint(Bs[n * SM_STRIDE + kcol]);
                    const uint32_t b1 = __float_as_uint(Bs[n * SM_STRIDE + kcol + 4]);
                    mma_tf32(acc[0][nj], a[0], b0, b1);
                    mma_tf32(acc[1][nj], a[1], b0, b1);
                }
            }
        }
        if (has_next) {
            float* As = sm + (cur ^ 1) * SM_STAGE;
            float* Bs = As + SM_TILE;
#pragma unroll
            for (int p = 0; p < 4; p++) {
                float4 t;
                t.x = f2tf32(va[p].x); t.y = f2tf32(va[p].y);
                t.z = f2tf32(va[p].z); t.w = f2tf32(va[p].w);
                *(float4*)&As[(aM + (p << 5)) * SM_STRIDE + aC4] = t;
                const int k = bK + (p << 3);
                Bs[(bN + 0) * SM_STRIDE + k] = f2tf32(vb[p].x);
                Bs[(bN + 1) * SM_STRIDE + k] = f2tf32(vb[p].y);
                Bs[(bN + 2) * SM_STRIDE + k] = f2tf32(vb[p].z);
                Bs[(bN + 3) * SM_STRIDE + k] = f2tf32(vb[p].w);
            }
        }
        __syncthreads();
    }

#pragma unroll
    for (int mi = 0; mi < 2; mi++) {
        const int row0 = bm + (warp_m << 5) + (mi << 4) + q;
#pragma unroll
        for (int nj = 0; nj < 8; nj++) {
            const int col = bn + (warp_n << 6) + (nj << 3) + (lp << 1);
            const float bx = bias[col];
            const float by = bias[col + 1];
            float2 v0 = make_float2(acc[mi][nj][0] + bx, acc[mi][nj][1] + by);
            float2 v1 = make_float2(acc[mi][nj][2] + bx, acc[mi][nj][3] + by);
            if (MODE == 0) {
                const int which = col / DIMC;
                const int cc = col - which * DIMC;
                const int hh = cc >> 6;
                const int dd = cc & 63;
                const int bb0 = row0 >> 11, nn0 = row0 & 2047;
                const int r1 = row0 + 8;
                const int bb1 = r1 >> 11, nn1 = r1 & 2047;
                const size_t base = (((size_t)which * BATCH) * NHEAD + hh) * SEQ * HDIM;
                *(float2*)&g_qkv[base + (((size_t)bb0 * NHEAD * SEQ) + nn0) * HDIM + dd] = v0;
                *(float2*)&g_qkv[base + (((size_t)bb1 * NHEAD * SEQ) + nn1) * HDIM + dd] = v1;
            } else {
                *(float2*)&Oout[(size_t)row0 * Nout + col] = v0;
                *(float2*)&Oout[(size_t)(row0 + 8) * Nout + col] = v1;
            }
        }
    }
}

// ---------------------------------------------------------------------------
// Flash attention on tf32 mma.sync.
// One CTA = (b, h, 128-query tile); 8 warps x 16 q-rows.
// Q fragments resident in registers for all 32 k-tiles.
// Smem strides chosen for conflict-free fragment LDS:
//   K/P (row index = lane>>2 pattern): stride 68 -> bank = lane
//   V   (row index = lane&3 pattern):  stride 72 -> bank = 8*(lane&3)+(lane>>2)
// ---------------------------------------------------------------------------
#define KS_STRIDE 68
#define V_STRIDE  72
#define P_STRIDE  68
#define OFF_V (64 * KS_STRIDE)
#define OFF_P (OFF_V + 64 * V_STRIDE)
#define ATTN_SMEM_BYTES ((OFF_P + 128 * P_STRIDE) * 4)   // 70656

__global__ __launch_bounds__(256, 1)
void attn_mma_kernel()
{
    extern __shared__ float sm[];
    float* Ks = sm;
    float* Vs = sm + OFF_V;
    float* Ps = sm + OFF_P;

    const int tid  = threadIdx.x;
    const int wid  = tid >> 5;
    const int lane = tid & 31;
    const int gq   = lane >> 2;     // 0..7
    const int gl   = lane & 3;      // 0..3
    const int q0   = blockIdx.x << 7;
    const int h    = blockIdx.y;
    const int b    = blockIdx.z;

    const size_t bh = ((size_t)b * NHEAD + h) * ((size_t)SEQ * HDIM);
    const float* Qg = g_qkv + bh + (size_t)q0 * HDIM;
    const float* Kg = g_qkv + QKV_ONE + bh;
    const float* Vg = g_qkv + 2 * QKV_ONE + bh;

    // ---- Stage Q (128x64) through Ps, load register fragments, pre-scaled ----
#pragma unroll
    for (int p = 0; p < 8; p++) {
        const int idx = tid + (p << 8);
        const int row = idx >> 4;
        const int c4  = (idx & 15) << 2;
        const float4 v = *(const float4*)(Qg + ((size_t)row << 6) + c4);
        float* d = &Ps[row * P_STRIDE + c4];
        d[0] = f2tf32(v.x * ATTN_SCALE);
        d[1] = f2tf32(v.y * ATTN_SCALE);
        d[2] = f2tf32(v.z * ATTN_SCALE);
        d[3] = f2tf32(v.w * ATTN_SCALE);
    }
    __syncthreads();

    const int qr = (wid << 4) + gq;      // warp-local base q row (and +8)
    uint32_t aq[8][4];
#pragma unroll
    for (int ks = 0; ks < 8; ks++) {
        const int kc = (ks << 3) + gl;
        aq[ks][0] = __float_as_uint(Ps[qr * P_STRIDE + kc]);
        aq[ks][1] = __float_as_uint(Ps[(qr + 8) * P_STRIDE + kc]);
        aq[ks][2] = __float_as_uint(Ps[qr * P_STRIDE + kc + 4]);
        aq[ks][3] = __float_as_uint(Ps[(qr + 8) * P_STRIDE + kc + 4]);
    }
    __syncthreads();   // done using Ps as Q stage

    // ---- K/V tile staging (64x64 each): 4 float4 per thread per tile ----
    const int sRow = tid >> 2;            // 0..63
    const int sC4  = (tid & 3) << 2;      // 0,4,8,12 ; +16 per p
    float4 pk[4], pv[4];
#pragma unroll
    for (int p = 0; p < 4; p++) {
        pk[p] = *(const float4*)(Kg + ((size_t)sRow << 6) + sC4 + (p << 4));
        pv[p] = *(const float4*)(Vg + ((size_t)sRow << 6) + sC4 + (p << 4));
    }
#pragma unroll
    for (int p = 0; p < 4; p++) {
        const int c = sC4 + (p << 4);
        float* dk = &Ks[sRow * KS_STRIDE + c];
        dk[0] = f2tf32(pk[p].x); dk[1] = f2tf32(pk[p].y);
        dk[2] = f2tf32(pk[p].z); dk[3] = f2tf32(pk[p].w);
        float* dv = &Vs[sRow * V_STRIDE + c];
        dv[0] = f2tf32(pv[p].x); dv[1] = f2tf32(pv[p].y);
        dv[2] = f2tf32(pv[p].z); dv[3] = f2tf32(pv[p].w);
    }
    __syncthreads();

    float Oacc[8][4];
#pragma unroll
    for (int nj = 0; nj < 8; nj++)
#pragma unroll
        for (int r = 0; r < 4; r++) Oacc[nj][r] = 0.0f;
    float m0 = -1e30f, m1 = -1e30f, l0 = 0.0f, l1 = 0.0f;

    for (int kt = 0; kt < SEQ / 64; kt++) {
        const bool has_next = (kt + 1 < SEQ / 64);
        if (has_next) {
            const float* Kt = Kg + (((size_t)(kt + 1)) << 6) * HDIM;
            const float* Vt = Vg + (((size_t)(kt + 1)) << 6) * HDIM;
#pragma unroll
            for (int p = 0; p < 4; p++) {
                pk[p] = *(const float4*)(Kt + ((size_t)sRow << 6) + sC4 + (p << 4));
                pv[p] = *(const float4*)(Vt + ((size_t)sRow << 6) + sC4 + (p << 4));
            }
        }

        // ---- S = Q K^T : 8 n-tiles x 8 k-steps ----
        float s[8][4];
#pragma unroll
        for (int nj = 0; nj < 8; nj++) {
            s[nj][0] = 0.0f; s[nj][1] = 0.0f; s[nj][2] = 0.0f; s[nj][3] = 0.0f;
            const int nrow = (nj << 3) + gq;
#pragma unroll
            for (int ks = 0; ks < 8; ks++) {
                const int kc = (ks << 3) + gl;
                const uint32_t b0 = __float_as_uint(Ks[nrow * KS_STRIDE + kc]);
                const uint32_t b1 = __float_as_uint(Ks[nrow * KS_STRIDE + kc + 4]);
                mma_tf32(s[nj], aq[ks], b0, b1);
            }
        }

        // ---- Online softmax (rows qr and qr+8, quad-reduced over lane bits 0,1) ----
        float c0 = -1e30f, c1 = -1e30f;
#pragma unroll
        for (int nj = 0; nj < 8; nj++) {
            c0 = fmaxf(c0, fmaxf(s[nj][0], s[nj][1]));
            c1 = fmaxf(c1, fmaxf(s[nj][2], s[nj][3]));
        }
        c0 = fmaxf(c0, __shfl_xor_sync(0xffffffffu, c0, 1));
        c0 = fmaxf(c0, __shfl_xor_sync(0xffffffffu, c0, 2));
        c1 = fmaxf(c1, __shfl_xor_sync(0xffffffffu, c1, 1));
        c1 = fmaxf(c1, __shfl_xor_sync(0xffffffffu, c1, 2));
        const float mn0 = fmaxf(m0, c0);
        const float mn1 = fmaxf(m1, c1);
        const float al0 = __expf(m0 - mn0);
        const float al1 = __expf(m1 - mn1);
        m0 = mn0; m1 = mn1;

        float r0 = 0.0f, r1 = 0.0f;
#pragma unroll
        for (int nj = 0; nj < 8; nj++) {
            s[nj][0] = __expf(s[nj][0] - mn0);
            s[nj][1] = __expf(s[nj][1] - mn0);
            s[nj][2] = __expf(s[nj][2] - mn1);
            s[nj][3] = __expf(s[nj][3] - mn1);
            r0 += s[nj][0] + s[nj][1];
            r1 += s[nj][2] + s[nj][3];
        }
        r0 += __shfl_xor_sync(0xffffffffu, r0, 1);
        r0 += __shfl_xor_sync(0xffffffffu, r0, 2);
        r1 += __shfl_xor_sync(0xffffffffu, r1, 1);
        r1 += __shfl_xor_sync(0xffffffffu, r1, 2);
        l0 = l0 * al0 + r0;
        l1 = l1 * al1 + r1;
#pragma unroll
        for (int nj = 0; nj < 8; nj++) {
            Oacc[nj][0] *= al0; Oacc[nj][1] *= al0;
            Oacc[nj][2] *= al1; Oacc[nj][3] *= al1;
        }

        // ---- P -> per-warp-private smem strip (rows qr, qr+8 only) ----
#pragma unroll
        for (int nj = 0; nj < 8; nj++) {
            const int col = (nj << 3) + (gl << 1);
            *(float2*)&Ps[qr * P_STRIDE + col] =
                make_float2(f2tf32(s[nj][0]), f2tf32(s[nj][1]));
            *(float2*)&Ps[(qr + 8) * P_STRIDE + col] =
                make_float2(f2tf32(s[nj][2]), f2tf32(s[nj][3]));
        }
        __syncwarp();

        // ---- O += P V : 8 k-steps (key) x 8 n-tiles (d) ----
#pragma unroll
        for (int ks = 0; ks < 8; ks++) {
            const int kc = (ks << 3) + gl;
            uint32_t pa[4];
            pa[0] = __float_as_uint(Ps[qr * P_STRIDE + kc]);
            pa[1] = __float_as_uint(Ps[(qr + 8) * P_STRIDE + kc]);
            pa[2] = __float_as_uint(Ps[qr * P_STRIDE + kc + 4]);
            pa[3] = __float_as_uint(Ps[(qr + 8) * P_STRIDE + kc + 4]);
#pragma unroll
            for (int nj = 0; nj < 8; nj++) {
                const int d = (nj << 3) + gq;
                const uint32_t b0 = __float_as_uint(Vs[((ks << 3) + gl) * V_STRIDE + d]);
                const uint32_t b1 = __float_as_uint(Vs[((ks << 3) + gl + 4) * V_STRIDE + d]);
                mma_tf32(Oacc[nj], pa, b0, b1);
            }
        }

        __syncthreads();   // all warps done with Ks/Vs
        if (has_next) {
#pragma unroll
            for (int p = 0; p < 4; p++) {
                const int c = sC4 + (p << 4);
                float* dk = &Ks[sRow * KS_STRIDE + c];
                dk[0] = f2tf32(pk[p].x); dk[1] = f2tf32(pk[p].y);
                dk[2] = f2tf32(pk[p].z); dk[3] = f2tf32(pk[p].w);
                float* dv = &Vs[sRow * V_STRIDE + c];
                dv[0] = f2tf32(pv[p].x); dv[1] = f2tf32(pv[p].y);
                dv[2] = f2tf32(pv[p].z); dv[3] = f2tf32(pv[p].w);
            }
            __syncthreads();
        }
    }

    // ---- Epilogue: normalize, write g_attn[b][n][h*64+d] ----
    const float inv0 = 1.0f / l0;
    const float inv1 = 1.0f / l1;
    const int n0 = q0 + qr;
    float* dst0 = &g_attn[((size_t)b * SEQ + n0) * DIMC + h * HDIM];
    float* dst1 = &g_attn[((size_t)b * SEQ + n0 + 8) * DIMC + h * HDIM];
#pragma unroll
    for (int nj = 0; nj < 8; nj++) {
        const int col = (nj << 3) + (gl << 1);
        *(float2*)(dst0 + col) = make_float2(Oacc[nj][0] * inv0, Oacc[nj][1] * inv0);
        *(float2*)(dst1 + col) = make_float2(Oacc[nj][2] * inv1, Oacc[nj][3] * inv1);
    }
}

// ---------------------------------------------------------------------------
extern "C" void kernel_launch(void* const* d_in, const int* in_sizes, int n_in,
                              void* d_out, int out_size)
{
    (void)in_sizes; (void)n_in; (void)out_size;
    const float* x      = (const float*)d_in[0];
    const float* w_qkv  = (const float*)d_in[1];
    const float* b_qkv  = (const float*)d_in[2];
    const float* w_proj = (const float*)d_in[3];
    const float* b_proj = (const float*)d_in[4];
    float* out = (float*)d_out;

    cudaFuncSetAttribute(mma_gemm<0>, cudaFuncAttributeMaxDynamicSharedMemorySize, GEMM_SMEM_BYTES);
    cudaFuncSetAttribute(mma_gemm<1>, cudaFuncAttributeMaxDynamicSharedMemorySize, GEMM_SMEM_BYTES);
    cudaFuncSetAttribute(attn_mma_kernel, cudaFuncAttributeMaxDynamicSharedMemorySize, ATTN_SMEM_BYTES);

    // 1) QKV GEMM (tf32 mma.sync): [4096,2560]@[2560,7680]+bias -> g_qkv
    {
        dim3 grid(MROWS / 128, 3 * DIMC / 128);
        mma_gemm<0><<<grid, 256, GEMM_SMEM_BYTES>>>(x, w_qkv, b_qkv, nullptr, 3 * DIMC);
    }
    // 2) Attention (tf32 mma.sync) -> g_attn
    {
        dim3 grid(SEQ / 128, NHEAD, BATCH);     // (16, 40, 2) = 1280 CTAs
        attn_mma_kernel<<<grid, 256, ATTN_SMEM_BYTES>>>();
    }
    // 3) Projection GEMM (tf32 mma.sync): [4096,2560]@[2560,2560]+bias -> d_out
    {
        dim3 grid(MROWS / 128, DIMC / 128);
        mma_gemm<1><<<grid, 256, GEMM_SMEM_BYTES>>>(nullptr, w_proj, b_proj, out, DIMC);
    }
}